// round 8
// baseline (speedup 1.0000x reference)
#include <cuda_runtime.h>
#include <cuda_bf16.h>
#include <cstdio>

#define D 128
#define ESZ 20
#define MAX_NODES 20000
#define MAX_EDGES 600000
#define CUTOFF 5.0f

// ---------------- scratch (static device bss; no allocations) ----------------
__device__ __align__(16) float g_h1 [MAX_NODES * D];
__device__ __align__(16) float g_so [MAX_NODES * 3 * D];
__device__ __align__(16) float g_s  [MAX_NODES * D];
__device__ __align__(16) float g_v  [MAX_NODES * 3 * D];
__device__ __align__(16) float g_Uv [MAX_NODES * 3 * D];
__device__ __align__(16) float g_Vv [MAX_NODES * 3 * D];
__device__ __align__(16) float g_cat[MAX_NODES * 2 * D];
__device__ __align__(16) float g_ip [MAX_NODES * D];
__device__ __align__(16) float g_h2 [MAX_NODES * D];
__device__ __align__(16) float g_a  [MAX_NODES * 3 * D];
// CSR scratch
__device__ int g_cnt [MAX_NODES];
__device__ int g_cur [MAX_NODES];
__device__ int g_off [MAX_NODES + 1];
__device__ int g_perm[MAX_EDGES];

// ---------------- helpers ----------------
__device__ __forceinline__ float silu_f(float x) {
    return x / (1.0f + __expf(-x));
}

// ---------------- CSR build ----------------
__global__ void csr_zero_kernel(int n) {
    int i = blockIdx.x * blockDim.x + threadIdx.x;
    if (i < n) { g_cnt[i] = 0; g_cur[i] = 0; }
}
__global__ void csr_hist_kernel(const int* __restrict__ eidx, int E) {
    int e = blockIdx.x * blockDim.x + threadIdx.x;
    if (e < E) atomicAdd(&g_cnt[eidx[2 * e + 1]], 1);
}
// single-CTA exclusive scan over n bins (1024 threads)
__global__ void csr_scan_kernel(int n) {
    __shared__ int sm[1024];
    int t = threadIdx.x;
    int per = (n + 1023) / 1024;
    int base = t * per;
    int sum = 0;
    for (int i = 0; i < per; i++) {
        int b = base + i;
        if (b < n) sum += g_cnt[b];
    }
    sm[t] = sum;
    __syncthreads();
    for (int off = 1; off < 1024; off <<= 1) {
        int v = 0;
        if (t >= off) v = sm[t - off];
        __syncthreads();
        if (t >= off) sm[t] += v;
        __syncthreads();
    }
    int run = (t == 0) ? 0 : sm[t - 1];
    for (int i = 0; i < per; i++) {
        int b = base + i;
        if (b < n) { g_off[b] = run; run += g_cnt[b]; }
    }
    if (t == 1023) g_off[n] = sm[1023];
}
__global__ void csr_scatter_kernel(const int* __restrict__ eidx, int E) {
    int e = blockIdx.x * blockDim.x + threadIdx.x;
    if (e < E) {
        int dst = eidx[2 * e + 1];
        int pos = g_off[dst] + atomicAdd(&g_cur[dst], 1);
        g_perm[pos] = e;
    }
}

// ---------------- generic tiled SGEMM ----------------
template<bool SILU, bool HASBIAS>
__global__ __launch_bounds__(256) void sgemm_kernel(
    const float* __restrict__ A, const float* __restrict__ B,
    const float* __restrict__ bias, float* __restrict__ C,
    int M, int N, int K)
{
    const int BM = 128, BN = 64, BK = 16, TM = 8, TN = 4;
    __shared__ __align__(16) float As[BK][BM + 4];
    __shared__ __align__(16) float Bs[BK][BN];
    int t = threadIdx.x;
    int tx = t & 15;
    int ty = t >> 4;
    int m0 = blockIdx.x * BM;
    int n0 = blockIdx.y * BN;

    float acc[TM][TN];
    #pragma unroll
    for (int i = 0; i < TM; i++)
        #pragma unroll
        for (int j = 0; j < TN; j++) acc[i][j] = 0.0f;

    for (int k0 = 0; k0 < K; k0 += BK) {
        #pragma unroll
        for (int it = 0; it < 2; it++) {
            int l = t + 256 * it;
            int row = l >> 2;
            int kc = (l & 3) * 4;
            float4 v = make_float4(0.f, 0.f, 0.f, 0.f);
            int gr = m0 + row;
            if (gr < M) v = *(const float4*)&A[(size_t)gr * K + k0 + kc];
            As[kc + 0][row] = v.x;
            As[kc + 1][row] = v.y;
            As[kc + 2][row] = v.z;
            As[kc + 3][row] = v.w;
        }
        {
            int row = t >> 4;
            int nc = (t & 15) * 4;
            float4 v = *(const float4*)&B[(size_t)(k0 + row) * N + n0 + nc];
            *(float4*)&Bs[row][nc] = v;
        }
        __syncthreads();
        #pragma unroll
        for (int k = 0; k < BK; k++) {
            float4 a0 = *(float4*)&As[k][ty * TM];
            float4 a1 = *(float4*)&As[k][ty * TM + 4];
            float4 b0 = *(float4*)&Bs[k][tx * TN];
            float ar[TM] = {a0.x, a0.y, a0.z, a0.w, a1.x, a1.y, a1.z, a1.w};
            float br[TN] = {b0.x, b0.y, b0.z, b0.w};
            #pragma unroll
            for (int i = 0; i < TM; i++)
                #pragma unroll
                for (int j = 0; j < TN; j++)
                    acc[i][j] += ar[i] * br[j];
        }
        __syncthreads();
    }

    float4 bv = make_float4(0.f, 0.f, 0.f, 0.f);
    if (HASBIAS) bv = *(const float4*)&bias[n0 + tx * TN];
    #pragma unroll
    for (int i = 0; i < TM; i++) {
        int gr = m0 + ty * TM + i;
        if (gr >= M) continue;
        float4 o;
        o.x = acc[i][0] + bv.x;
        o.y = acc[i][1] + bv.y;
        o.z = acc[i][2] + bv.z;
        o.w = acc[i][3] + bv.w;
        if (SILU) { o.x = silu_f(o.x); o.y = silu_f(o.y); o.z = silu_f(o.z); o.w = silu_f(o.w); }
        *(float4*)&C[(size_t)gr * N + n0 + tx * TN] = o;
    }
}

// ---------------- dual SGEMM: C1 = A@B1, C2 = A@B2 ----------------
__global__ __launch_bounds__(256) void sgemm_dual_kernel(
    const float* __restrict__ A,
    const float* __restrict__ B1, const float* __restrict__ B2,
    float* __restrict__ C1, float* __restrict__ C2,
    int M, int N, int K)
{
    const int BM = 128, BN = 64, BK = 16, TM = 8, TN = 4;
    __shared__ __align__(16) float As[BK][BM + 4];
    __shared__ __align__(16) float Bs1[BK][BN];
    __shared__ __align__(16) float Bs2[BK][BN];
    int t = threadIdx.x;
    int tx = t & 15;
    int ty = t >> 4;
    int m0 = blockIdx.x * BM;
    int n0 = blockIdx.y * BN;

    float acc1[TM][TN], acc2[TM][TN];
    #pragma unroll
    for (int i = 0; i < TM; i++)
        #pragma unroll
        for (int j = 0; j < TN; j++) { acc1[i][j] = 0.0f; acc2[i][j] = 0.0f; }

    for (int k0 = 0; k0 < K; k0 += BK) {
        #pragma unroll
        for (int it = 0; it < 2; it++) {
            int l = t + 256 * it;
            int row = l >> 2;
            int kc = (l & 3) * 4;
            float4 v = make_float4(0.f, 0.f, 0.f, 0.f);
            int gr = m0 + row;
            if (gr < M) v = *(const float4*)&A[(size_t)gr * K + k0 + kc];
            As[kc + 0][row] = v.x;
            As[kc + 1][row] = v.y;
            As[kc + 2][row] = v.z;
            As[kc + 3][row] = v.w;
        }
        {
            int row = t >> 4;
            int nc = (t & 15) * 4;
            *(float4*)&Bs1[row][nc] = *(const float4*)&B1[(size_t)(k0 + row) * N + n0 + nc];
            *(float4*)&Bs2[row][nc] = *(const float4*)&B2[(size_t)(k0 + row) * N + n0 + nc];
        }
        __syncthreads();
        #pragma unroll
        for (int k = 0; k < BK; k++) {
            float4 a0 = *(float4*)&As[k][ty * TM];
            float4 a1 = *(float4*)&As[k][ty * TM + 4];
            float ar[TM] = {a0.x, a0.y, a0.z, a0.w, a1.x, a1.y, a1.z, a1.w};
            float4 b1 = *(float4*)&Bs1[k][tx * TN];
            float4 b2 = *(float4*)&Bs2[k][tx * TN];
            float br1[TN] = {b1.x, b1.y, b1.z, b1.w};
            float br2[TN] = {b2.x, b2.y, b2.z, b2.w};
            #pragma unroll
            for (int i = 0; i < TM; i++)
                #pragma unroll
                for (int j = 0; j < TN; j++) {
                    acc1[i][j] += ar[i] * br1[j];
                    acc2[i][j] += ar[i] * br2[j];
                }
        }
        __syncthreads();
    }

    #pragma unroll
    for (int i = 0; i < TM; i++) {
        int gr = m0 + ty * TM + i;
        if (gr >= M) continue;
        float4 o1, o2;
        o1.x = acc1[i][0]; o1.y = acc1[i][1]; o1.z = acc1[i][2]; o1.w = acc1[i][3];
        o2.x = acc2[i][0]; o2.y = acc2[i][1]; o2.z = acc2[i][2]; o2.w = acc2[i][3];
        *(float4*)&C1[(size_t)gr * N + n0 + tx * TN] = o1;
        *(float4*)&C2[(size_t)gr * N + n0 + tx * TN] = o2;
    }
}

// ---------------- node-centric fused message kernel (v4, atomic-free) ----------------
// CTA owns NPC consecutive dst nodes. For each node: iterate its CSR in-edges in
// chunks of EB. Phase 1 (threads 0..95, 4 cols each, Wf in regs) computes
// filter_output into smem. Phase 2 (128 threads, one float4 slot each:
// t<32 -> messages_scalar chans 4t.., t>=32 -> component (t>>5)-1 chans 4(t&31)..)
// accumulates in registers. Flush: plain vectorized store of ns/nsv + acc.
#define NPC 8
#define EB 16
__global__ void __launch_bounds__(128, 5) msg_kernel(
    const float* __restrict__ es_g, const float* __restrict__ ev_g,
    const float* __restrict__ norms, const int* __restrict__ eidx,
    const float* __restrict__ Wf, const float* __restrict__ bf,
    const float* __restrict__ ns, const float* __restrict__ nsv,
    int n, int E)
{
    __shared__ __align__(16) float es_sh[EB][ESZ];   // 80B rows, 16B aligned
    __shared__ __align__(16) float fo_sh[EB][3 * D];
    __shared__ int   src_sh[EB];
    __shared__ float ev_sh[EB][3];
    __shared__ float fc_sh[EB];

    int t = threadIdx.x;
    bool filt = (t < 96);
    int s = t & 31;                 // phase-2 slot within group
    int comp = (t >> 5) - 1;        // -1: scalar group; 0..2: vector component

    // Wf columns (4 consecutive) in registers for filter threads
    float wf_r[ESZ][4];
    float4 bf4 = make_float4(0.f, 0.f, 0.f, 0.f);
    if (filt) {
        #pragma unroll
        for (int k = 0; k < ESZ; k++) {
            float4 w = *(const float4*)&Wf[k * 384 + 4 * t];
            wf_r[k][0] = w.x; wf_r[k][1] = w.y; wf_r[k][2] = w.z; wf_r[k][3] = w.w;
        }
        bf4 = *(const float4*)&bf[4 * t];
    }

    int n0 = blockIdx.x * NPC;
    int n1 = min(n0 + NPC, n);

    for (int nd = n0; nd < n1; nd++) {
        int ebeg = g_off[nd];
        int eend = g_off[nd + 1];
        float4 acc = make_float4(0.f, 0.f, 0.f, 0.f);

        for (int c0 = ebeg; c0 < eend; c0 += EB) {
            int m = min(EB, eend - c0);

            // ---- stage: threads 0..m-1 each own one edge ----
            if (t < m) {
                int eid = g_perm[c0 + t];
                src_sh[t] = eidx[2 * eid];
                ev_sh[t][0] = __ldg(&ev_g[3 * eid]);
                ev_sh[t][1] = __ldg(&ev_g[3 * eid + 1]);
                ev_sh[t][2] = __ldg(&ev_g[3 * eid + 2]);
                float nrm = __ldg(&norms[eid]);
                fc_sh[t] = (nrm < CUTOFF) ? 0.5f * (cospif(nrm / CUTOFF) + 1.0f) : 0.0f;
                const float4* ep = (const float4*)&es_g[(size_t)eid * ESZ];
                float4* dp = (float4*)&es_sh[t][0];
                #pragma unroll
                for (int q = 0; q < 5; q++) dp[q] = __ldg(&ep[q]);
            }
            __syncthreads();

            // ---- phase 1: filter_output ----
            if (filt) {
                #pragma unroll 2
                for (int j = 0; j < EB; j++) {
                    if (j >= m) break;
                    int src = src_sh[j];
                    float4 so = __ldg((const float4*)&g_so[(size_t)src * 384 + 4 * t]);
                    float4 a = bf4;
                    #pragma unroll
                    for (int k = 0; k < ESZ; k++) {
                        float ek = es_sh[j][k];
                        a.x = fmaf(ek, wf_r[k][0], a.x);
                        a.y = fmaf(ek, wf_r[k][1], a.y);
                        a.z = fmaf(ek, wf_r[k][2], a.z);
                        a.w = fmaf(ek, wf_r[k][3], a.w);
                    }
                    float fc = fc_sh[j];
                    float4 fo;
                    fo.x = a.x * fc * so.x;
                    fo.y = a.y * fc * so.y;
                    fo.z = a.z * fc * so.z;
                    fo.w = a.w * fc * so.w;
                    *(float4*)&fo_sh[j][4 * t] = fo;
                }
            }
            __syncthreads();

            // ---- phase 2: accumulate into registers ----
            if (t < 32) {
                #pragma unroll 4
                for (int j = 0; j < EB; j++) {
                    if (j >= m) break;
                    float4 ms = *(float4*)&fo_sh[j][2 * D + 4 * s];
                    acc.x += ms.x; acc.y += ms.y; acc.z += ms.z; acc.w += ms.w;
                }
            } else {
                #pragma unroll 4
                for (int j = 0; j < EB; j++) {
                    if (j >= m) break;
                    int src = src_sh[j];
                    float4 gn = *(float4*)&fo_sh[j][4 * s];
                    float4 ge = *(float4*)&fo_sh[j][D + 4 * s];
                    float evc = ev_sh[j][comp];
                    float4 nv = __ldg((const float4*)&nsv[((size_t)src * 3 + comp) * D + 4 * s]);
                    acc.x = fmaf(nv.x, gn.x, fmaf(ge.x, evc, acc.x));
                    acc.y = fmaf(nv.y, gn.y, fmaf(ge.y, evc, acc.y));
                    acc.z = fmaf(nv.z, gn.z, fmaf(ge.z, evc, acc.z));
                    acc.w = fmaf(nv.w, gn.w, fmaf(ge.w, evc, acc.w));
                }
            }
            __syncthreads();
        }

        // ---- flush: s = ns + ds_m ; v = nsv + dv_m (plain stores) ----
        if (t < 32) {
            float4 b = *(const float4*)&ns[(size_t)nd * D + 4 * s];
            b.x += acc.x; b.y += acc.y; b.z += acc.z; b.w += acc.w;
            *(float4*)&g_s[(size_t)nd * D + 4 * s] = b;
        } else {
            size_t idx = ((size_t)nd * 3 + comp) * D + 4 * s;
            float4 b = *(const float4*)&nsv[idx];
            b.x += acc.x; b.y += acc.y; b.z += acc.z; b.w += acc.w;
            *(float4*)&g_v[idx] = b;
        }
    }
}

// ---------------- per-node: Vv_sq, ip, concat ----------------
__global__ void vsq_ip_cat_kernel(int n) {
    int node = blockIdx.x;
    int i = threadIdx.x;  // 128
    float vsq = 0.f, ipv = 0.f;
    #pragma unroll
    for (int c = 0; c < 3; c++) {
        float u = g_Uv[((size_t)node * 3 + c) * D + i];
        float w = g_Vv[((size_t)node * 3 + c) * D + i];
        vsq += w * w;
        ipv += u * w;
    }
    g_cat[(size_t)node * 256 + i]       = g_s[(size_t)node * D + i];
    g_cat[(size_t)node * 256 + D + i]   = vsq;
    g_ip[(size_t)node * D + i]          = ipv;
}

// ---------------- final elementwise ----------------
__global__ void final_kernel(float* __restrict__ out, int n) {
    int node = blockIdx.x;
    int i = threadIdx.x;  // 128
    const float* a = &g_a[(size_t)node * 384];
    float a_ss = a[i];
    float a_sv = a[D + i];
    float a_vv = a[2 * D + i];
    out[(size_t)node * D + i] =
        g_s[(size_t)node * D + i] + a_ss + a_sv * g_ip[(size_t)node * D + i];
    float* vout = out + (size_t)n * D;
    #pragma unroll
    for (int c = 0; c < 3; c++) {
        size_t idx = ((size_t)node * 3 + c) * D + i;
        vout[idx] = g_v[idx] + a_vv * g_Uv[idx];
    }
}

// ---------------- launch ----------------
extern "C" void kernel_launch(void* const* d_in, const int* in_sizes, int n_in,
                              void* d_out, int out_size) {
    const float* ns  = (const float*)d_in[0];
    const float* nv  = (const float*)d_in[1];
    const float* es  = (const float*)d_in[2];
    const float* ev  = (const float*)d_in[3];
    const float* en  = (const float*)d_in[4];
    const int*   ei  = (const int*)  d_in[5];
    const float* Wf  = (const float*)d_in[6];
    const float* bf  = (const float*)d_in[7];
    const float* Wm1 = (const float*)d_in[8];
    const float* bm1 = (const float*)d_in[9];
    const float* Wm2 = (const float*)d_in[10];
    const float* bm2 = (const float*)d_in[11];
    const float* WU  = (const float*)d_in[12];
    const float* WV  = (const float*)d_in[13];
    const float* Wa1 = (const float*)d_in[14];
    const float* ba1 = (const float*)d_in[15];
    const float* Wa2 = (const float*)d_in[16];
    const float* ba2 = (const float*)d_in[17];

    int n = in_sizes[0] / D;
    int E = in_sizes[4];
    float* out = (float*)d_out;

    float *p_h1, *p_so, *p_v, *p_Uv, *p_Vv, *p_cat, *p_h2, *p_a;
    cudaGetSymbolAddress((void**)&p_h1,  g_h1);
    cudaGetSymbolAddress((void**)&p_so,  g_so);
    cudaGetSymbolAddress((void**)&p_v,   g_v);
    cudaGetSymbolAddress((void**)&p_Uv,  g_Uv);
    cudaGetSymbolAddress((void**)&p_Vv,  g_Vv);
    cudaGetSymbolAddress((void**)&p_cat, g_cat);
    cudaGetSymbolAddress((void**)&p_h2,  g_h2);
    cudaGetSymbolAddress((void**)&p_a,   g_a);

    // --- CSR build (dst-sorted edge permutation) ---
    csr_zero_kernel<<<(n + 255) / 256, 256>>>(n);
    csr_hist_kernel<<<(E + 255) / 256, 256>>>(ei, E);
    csr_scan_kernel<<<1, 1024>>>(n);
    csr_scatter_kernel<<<(E + 255) / 256, 256>>>(ei, E);

    // 2. H1 = silu(ns @ Wm1 + bm1)
    {
        dim3 grid((n + 127) / 128, 128 / 64);
        sgemm_kernel<true, true><<<grid, 256>>>(ns, Wm1, bm1, p_h1, n, 128, 128);
    }
    // 3. SO = H1 @ Wm2 + bm2
    {
        dim3 grid((n + 127) / 128, 384 / 64);
        sgemm_kernel<false, true><<<grid, 256>>>(p_h1, Wm2, bm2, p_so, n, 384, 128);
    }
    // 4. node-centric fused message kernel (writes g_s = ns + ds, g_v = nv + dv)
    {
        int grid = (n + NPC - 1) / NPC;
        msg_kernel<<<grid, 128>>>(es, ev, en, ei, Wf, bf, ns, nv, n, E);
    }
    // 5/6. Uv = v @ WU, Vv = v @ WV
    {
        dim3 grid((3 * n + 127) / 128, 128 / 64);
        sgemm_dual_kernel<<<grid, 256>>>(p_v, WU, WV, p_Uv, p_Vv, 3 * n, 128, 128);
    }
    // 7. Vv_sq, ip, cat
    vsq_ip_cat_kernel<<<n, 128>>>(n);

    // 8. H2 = silu(cat @ Wa1 + ba1)
    {
        dim3 grid((n + 127) / 128, 128 / 64);
        sgemm_kernel<true, true><<<grid, 256>>>(p_cat, Wa1, ba1, p_h2, n, 128, 256);
    }
    // 9. A = H2 @ Wa2 + ba2
    {
        dim3 grid((n + 127) / 128, 384 / 64);
        sgemm_kernel<false, true><<<grid, 256>>>(p_h2, Wa2, ba2, p_a, n, 384, 128);
    }
    // 10. final
    final_kernel<<<n, 128>>>(out, n);
}